// round 1
// baseline (speedup 1.0000x reference)
#include <cuda_runtime.h>

#define H2   1024
#define SEQN 65536
#define OCH  8

// Scratch (allocation-free rule: device globals)
__device__ float    g_vpart[OCH][H2];
__device__ float    g_energy[SEQN];
__device__ unsigned g_maxord;
__device__ float    g_psum[256];

__device__ __forceinline__ unsigned ordf(float f) {
    unsigned u = __float_as_uint(f);
    return (u & 0x80000000u) ? ~u : (u | 0x80000000u);
}
__device__ __forceinline__ float unordf(unsigned u) {
    return __uint_as_float((u & 0x80000000u) ? (u ^ 0x80000000u) : ~u);
}

// K1: partial v[h] = sum over an o-chunk of W[o][h] * wv[o].
// grid (H2/256, OCH), 256 threads. Coalesced W reads. Deterministic (no atomics).
__global__ void k1_v(const float* __restrict__ W, const float* __restrict__ wv) {
    if (blockIdx.x == 0 && blockIdx.y == 0 && threadIdx.x == 0) g_maxord = 0u;  // ordered -max
    int h  = blockIdx.x * 256 + threadIdx.x;
    int o0 = blockIdx.y * (H2 / OCH);
    float acc = 0.f;
#pragma unroll 4
    for (int o = o0; o < o0 + H2 / OCH; o++)
        acc = fmaf(W[(size_t)o * H2 + h], __ldg(&wv[o]), acc);
    g_vpart[blockIdx.y][h] = acc;
}

// K2: e[row] = dot(outputs[row], v); also global max via ordered-uint atomicMax.
// grid SEQN/32 = 2048 blocks, 256 threads (8 warps x 4 rows each).
__global__ void k2_energy(const float* __restrict__ outs) {
    __shared__ __align__(16) float sv[H2];
    for (int i = threadIdx.x; i < H2; i += 256) {
        float s = 0.f;
#pragma unroll
        for (int c = 0; c < OCH; c++) s += g_vpart[c][i];  // deterministic v reduce
        sv[i] = s;
    }
    __syncthreads();

    const int warp = threadIdx.x >> 5, lane = threadIdx.x & 31;
    const float4* sv4 = (const float4*)sv;
    float wmax = -3.402823e38f;
    int base_row = blockIdx.x * 32 + warp * 4;
#pragma unroll
    for (int r = 0; r < 4; r++) {
        int row = base_row + r;
        const float4* p = (const float4*)(outs + (size_t)row * H2);
        float acc = 0.f;
#pragma unroll
        for (int it = 0; it < 8; it++) {
            float4 x = p[it * 32 + lane];
            float4 v = sv4[it * 32 + lane];
            acc = fmaf(x.x, v.x, acc); acc = fmaf(x.y, v.y, acc);
            acc = fmaf(x.z, v.z, acc); acc = fmaf(x.w, v.w, acc);
        }
#pragma unroll
        for (int off = 16; off; off >>= 1) acc += __shfl_xor_sync(0xffffffffu, acc, off);
        if (lane == 0) g_energy[row] = acc;
        wmax = fmaxf(wmax, acc);
    }
    __shared__ float smax[8];
    if (lane == 0) smax[warp] = wmax;
    __syncthreads();
    if (threadIdx.x == 0) {
        float m = smax[0];
#pragma unroll
        for (int i = 1; i < 8; i++) m = fmaxf(m, smax[i]);
        atomicMax(&g_maxord, ordf(m));  // max is order-independent -> deterministic
    }
}

// K3: out[i] = exp(e[i] - max); per-block partial sums (fixed-tree, deterministic).
// grid 256, 256 threads -> 1 element per thread.
__global__ void k3_exp(float* __restrict__ out) {
    int i = blockIdx.x * 256 + threadIdx.x;
    float m = unordf(g_maxord);
    float e = __expf(g_energy[i] - m);
    out[i] = e;
    __shared__ float ss[256];
    ss[threadIdx.x] = e;
    __syncthreads();
    for (int s = 128; s; s >>= 1) {
        if (threadIdx.x < s) ss[threadIdx.x] += ss[threadIdx.x + s];
        __syncthreads();
    }
    if (threadIdx.x == 0) g_psum[blockIdx.x] = ss[0];
}

// K4: every block redundantly reduces the 256 partials (deterministic tree),
// then normalizes its slice. grid 256, 256 threads.
__global__ void k4_norm(float* __restrict__ out) {
    __shared__ float ss[256];
    ss[threadIdx.x] = g_psum[threadIdx.x];
    __syncthreads();
    for (int s = 128; s; s >>= 1) {
        if (threadIdx.x < s) ss[threadIdx.x] += ss[threadIdx.x + s];
        __syncthreads();
    }
    float inv = 1.0f / ss[0];
    int i = blockIdx.x * 256 + threadIdx.x;
    out[i] *= inv;
}

extern "C" void kernel_launch(void* const* d_in, const int* in_sizes, int n_in,
                              void* d_out, int out_size) {
    const float* outputs = (const float*)d_in[0];   // [SEQ, 2H]
    const float* W       = (const float*)d_in[1];   // [2H, 2H]
    // d_in[2] = b: cancels exactly in softmax (constant shift) -> unused
    const float* wv      = (const float*)d_in[3];   // [1, 2H]
    float* out = (float*)d_out;                     // [1,1,SEQ] float32

    dim3 g1(H2 / 256, OCH);
    k1_v<<<g1, 256>>>(W, wv);
    k2_energy<<<SEQN / 32, 256>>>(outputs);
    k3_exp<<<256, 256>>>(out);
    k4_norm<<<256, 256>>>(out);
}

// round 2
// speedup vs baseline: 1.4367x; 1.4367x over previous
#include <cuda_runtime.h>

#define H2    1024
#define SEQN  65536
#define NCHK  32          // o-chunks for K1
#define NB3   64          // blocks for K3/K4

// Scratch (allocation-free rule: device globals)
__device__ float    g_vpart[NCHK][H2];
__device__ float    g_v[H2];
__device__ float    g_energy[SEQN];
__device__ unsigned g_maxord;
__device__ float    g_psum[NB3];

__device__ __forceinline__ unsigned ordf(float f) {
    unsigned u = __float_as_uint(f);
    return (u & 0x80000000u) ? ~u : (u | 0x80000000u);
}
__device__ __forceinline__ float unordf(unsigned u) {
    return __uint_as_float((u & 0x80000000u) ? (u ^ 0x80000000u) : ~u);
}

// K1: partial v[h] over one 32-wide o-chunk. grid (H2/256, NCHK)=(4,32), 256 thr.
// Fully unrolled -> 32 independent loads in flight. Coalesced W reads.
__global__ void k1_v(const float* __restrict__ W, const float* __restrict__ wv) {
    int h  = blockIdx.x * 256 + threadIdx.x;
    int o0 = blockIdx.y * (H2 / NCHK);
    float acc = 0.f;
#pragma unroll
    for (int i = 0; i < H2 / NCHK; i++)
        acc = fmaf(W[(size_t)(o0 + i) * H2 + h], __ldg(&wv[o0 + i]), acc);
    g_vpart[blockIdx.y][h] = acc;
}

// K1b: fold 32 partials into g_v (deterministic fixed order). grid 4, 256 thr.
__global__ void k1b_fold(void) {
    int h = blockIdx.x * 256 + threadIdx.x;
    float s = 0.f;
#pragma unroll
    for (int c = 0; c < NCHK; c++) s += g_vpart[c][h];
    g_v[h] = s;
    if (h == 0) g_maxord = 0u;  // ordered -inf
}

// K2: e[row] = dot(outputs[row], v). grid SEQN/32 = 2048 blocks, 256 threads.
// 8 warps x 4 rows each, all 4 rows accumulated concurrently (MLP ~32/lane).
__global__ void __launch_bounds__(256) k2_energy(const float* __restrict__ outs) {
    __shared__ __align__(16) float sv[H2];
    {
        float4 t = ((const float4*)g_v)[threadIdx.x];
        ((float4*)sv)[threadIdx.x] = t;
    }
    __syncthreads();

    const int warp = threadIdx.x >> 5, lane = threadIdx.x & 31;
    const float4* sv4 = (const float4*)sv;
    const int base_row = blockIdx.x * 32 + warp * 4;
    const float4* p0 = (const float4*)(outs + (size_t)(base_row + 0) * H2);
    const float4* p1 = (const float4*)(outs + (size_t)(base_row + 1) * H2);
    const float4* p2 = (const float4*)(outs + (size_t)(base_row + 2) * H2);
    const float4* p3 = (const float4*)(outs + (size_t)(base_row + 3) * H2);

    float a0 = 0.f, a1 = 0.f, a2 = 0.f, a3 = 0.f;
#pragma unroll
    for (int it = 0; it < 8; it++) {
        const int j = it * 32 + lane;
        float4 v = sv4[j];
        float4 x0 = p0[j], x1 = p1[j], x2 = p2[j], x3 = p3[j];
        a0 = fmaf(x0.x, v.x, a0); a0 = fmaf(x0.y, v.y, a0);
        a0 = fmaf(x0.z, v.z, a0); a0 = fmaf(x0.w, v.w, a0);
        a1 = fmaf(x1.x, v.x, a1); a1 = fmaf(x1.y, v.y, a1);
        a1 = fmaf(x1.z, v.z, a1); a1 = fmaf(x1.w, v.w, a1);
        a2 = fmaf(x2.x, v.x, a2); a2 = fmaf(x2.y, v.y, a2);
        a2 = fmaf(x2.z, v.z, a2); a2 = fmaf(x2.w, v.w, a2);
        a3 = fmaf(x3.x, v.x, a3); a3 = fmaf(x3.y, v.y, a3);
        a3 = fmaf(x3.z, v.z, a3); a3 = fmaf(x3.w, v.w, a3);
    }
#pragma unroll
    for (int off = 16; off; off >>= 1) {
        a0 += __shfl_xor_sync(0xffffffffu, a0, off);
        a1 += __shfl_xor_sync(0xffffffffu, a1, off);
        a2 += __shfl_xor_sync(0xffffffffu, a2, off);
        a3 += __shfl_xor_sync(0xffffffffu, a3, off);
    }
    if (lane == 0) {
        g_energy[base_row + 0] = a0;
        g_energy[base_row + 1] = a1;
        g_energy[base_row + 2] = a2;
        g_energy[base_row + 3] = a3;
    }
    float wmax = fmaxf(fmaxf(a0, a1), fmaxf(a2, a3));
    __shared__ float smax[8];
    if (lane == 0) smax[warp] = wmax;
    __syncthreads();
    if (threadIdx.x == 0) {
        float m = smax[0];
#pragma unroll
        for (int i = 1; i < 8; i++) m = fmaxf(m, smax[i]);
        atomicMax(&g_maxord, ordf(m));  // max: order-independent -> deterministic
    }
}

// K3: out = exp(e - max), per-block partial sums. grid NB3=64, 256 thr, float4.
__global__ void k3_exp(float* __restrict__ out) {
    int idx = blockIdx.x * 256 + threadIdx.x;          // float4 index
    float m = unordf(g_maxord);
    float4 e = ((const float4*)g_energy)[idx];
    float4 r;
    r.x = __expf(e.x - m); r.y = __expf(e.y - m);
    r.z = __expf(e.z - m); r.w = __expf(e.w - m);
    ((float4*)out)[idx] = r;
    __shared__ float ss[256];
    ss[threadIdx.x] = (r.x + r.y) + (r.z + r.w);
    __syncthreads();
    for (int s = 128; s; s >>= 1) {
        if (threadIdx.x < s) ss[threadIdx.x] += ss[threadIdx.x + s];
        __syncthreads();
    }
    if (threadIdx.x == 0) g_psum[blockIdx.x] = ss[0];
}

// K4: redundant deterministic reduce of 64 partials, then normalize. grid 64.
__global__ void k4_norm(float* __restrict__ out) {
    __shared__ float ss[NB3];
    if (threadIdx.x < NB3) ss[threadIdx.x] = g_psum[threadIdx.x];
    __syncthreads();
    for (int s = NB3 / 2; s; s >>= 1) {
        if (threadIdx.x < s) ss[threadIdx.x] += ss[threadIdx.x + s];
        __syncthreads();
    }
    float inv = 1.0f / ss[0];
    int idx = blockIdx.x * 256 + threadIdx.x;          // float4 index
    float4 r = ((const float4*)out)[idx];
    r.x *= inv; r.y *= inv; r.z *= inv; r.w *= inv;
    ((float4*)out)[idx] = r;
}

extern "C" void kernel_launch(void* const* d_in, const int* in_sizes, int n_in,
                              void* d_out, int out_size) {
    const float* outputs = (const float*)d_in[0];   // [SEQ, 2H]
    const float* W       = (const float*)d_in[1];   // [2H, 2H]
    // d_in[2] = b: constant shift, cancels in softmax -> unused
    const float* wv      = (const float*)d_in[3];   // [1, 2H]
    float* out = (float*)d_out;                     // [1,1,SEQ] float32

    k1_v<<<dim3(H2 / 256, NCHK), 256>>>(W, wv);
    k1b_fold<<<H2 / 256, 256>>>();
    k2_energy<<<SEQN / 32, 256>>>(outputs);
    k3_exp<<<NB3, 256>>>(out);
    k4_norm<<<NB3, 256>>>(out);
}